// round 1
// baseline (speedup 1.0000x reference)
#include <cuda_runtime.h>
#include <math.h>

#define N_NODES 50000
#define N_EDGES 800000
#define M_TOTAL (N_EDGES + N_NODES)   // 850000 with self loops
#define D_IN    128
#define F_OUT   256                   // HEADS * C
#define HEADS   8
#define CDIM    32
#define NEG_SLOPE 0.2f

// ---------------- scratch (static device globals; no allocation allowed) ----
__device__ float g_h[N_NODES * F_OUT];        // 51.2 MB
__device__ float g_asrc[N_NODES * HEADS];
__device__ float g_adst[N_NODES * HEADS];
__device__ int   g_deg[N_NODES];
__device__ int   g_off[N_NODES + 1];
__device__ int   g_cursor[N_NODES];
__device__ int   g_csr_src[M_TOTAL];
__device__ float g_pooled[F_OUT];

// ---------------- K0: zero scratch (graph replays => must re-init) ---------
__global__ void k_init() {
    int i = blockIdx.x * blockDim.x + threadIdx.x;
    if (i < N_NODES) { g_deg[i] = 0; g_cursor[i] = 0; }
    if (i < F_OUT)   g_pooled[i] = 0.0f;
}

// ---------------- K1: h = x @ W  (BM=64, BN=256, BK=128 full-K) ------------
// smem: xs 64x128 (32KB) + ws 128x256 (128KB) = 160KB  -> 1 block/SM
__global__ __launch_bounds__(256, 1)
void k_gemm(const float* __restrict__ x, const float* __restrict__ W) {
    extern __shared__ float sm[];
    float* xs = sm;              // [64][128]
    float* ws = sm + 64 * 128;   // [128][256]
    const int tid  = threadIdx.x;
    const int row0 = blockIdx.x * 64;

    // load all of W (32768 floats)
    const float4* W4  = (const float4*)W;
    float4*       ws4 = (float4*)ws;
    #pragma unroll 4
    for (int i = tid; i < 8192; i += 256) ws4[i] = W4[i];

    // load x tile (64 rows x 128)
    const float4* X4  = (const float4*)x;
    float4*       xs4 = (float4*)xs;
    #pragma unroll
    for (int i = tid; i < 2048; i += 256) {
        int r = i >> 5, c = i & 31;
        int gr = row0 + r;
        xs4[i] = (gr < N_NODES) ? X4[gr * 32 + c] : make_float4(0.f, 0.f, 0.f, 0.f);
    }
    __syncthreads();

    const int tx = tid & 31, ty = tid >> 5;
    float acc[8][8];
    #pragma unroll
    for (int i = 0; i < 8; i++)
        #pragma unroll
        for (int j = 0; j < 8; j++) acc[i][j] = 0.f;

    const float* xrow = xs + (ty * 8) * 128;
    #pragma unroll 2
    for (int kk = 0; kk < 128; kk += 4) {
        float4 a[8];
        #pragma unroll
        for (int i = 0; i < 8; i++) a[i] = *(const float4*)(xrow + i * 128 + kk);
        #pragma unroll
        for (int dk = 0; dk < 4; dk++) {
            float4 b0 = *(const float4*)(ws + (kk + dk) * 256 + tx * 4);
            float4 b1 = *(const float4*)(ws + (kk + dk) * 256 + 128 + tx * 4);
            #pragma unroll
            for (int i = 0; i < 8; i++) {
                float av = (dk == 0) ? a[i].x : (dk == 1) ? a[i].y : (dk == 2) ? a[i].z : a[i].w;
                acc[i][0] += av * b0.x; acc[i][1] += av * b0.y;
                acc[i][2] += av * b0.z; acc[i][3] += av * b0.w;
                acc[i][4] += av * b1.x; acc[i][5] += av * b1.y;
                acc[i][6] += av * b1.z; acc[i][7] += av * b1.w;
            }
        }
    }

    #pragma unroll
    for (int i = 0; i < 8; i++) {
        int r = row0 + ty * 8 + i;
        if (r < N_NODES) {
            float4 v0 = make_float4(acc[i][0], acc[i][1], acc[i][2], acc[i][3]);
            float4 v1 = make_float4(acc[i][4], acc[i][5], acc[i][6], acc[i][7]);
            *(float4*)(g_h + r * 256 + tx * 4)       = v0;
            *(float4*)(g_h + r * 256 + 128 + tx * 4) = v1;
        }
    }
}

// ---------------- K2: a_src/a_dst per node (warp per node) -----------------
__global__ __launch_bounds__(256)
void k_att(const float* __restrict__ att_src, const float* __restrict__ att_dst) {
    const int warp = threadIdx.x >> 5, lane = threadIdx.x & 31;
    const int node = blockIdx.x * 8 + warp;   // grid = 6250 -> exact
    const float4* hp = (const float4*)(g_h + node * 256 + lane * 8);
    float4 h0 = hp[0], h1 = hp[1];
    const float4* s4 = (const float4*)(att_src + lane * 8);
    const float4* d4 = (const float4*)(att_dst + lane * 8);
    float4 s0 = s4[0], s1 = s4[1], d0 = d4[0], d1 = d4[1];
    float ps = h0.x * s0.x + h0.y * s0.y + h0.z * s0.z + h0.w * s0.w
             + h1.x * s1.x + h1.y * s1.y + h1.z * s1.z + h1.w * s1.w;
    float pd = h0.x * d0.x + h0.y * d0.y + h0.z * d0.z + h0.w * d0.w
             + h1.x * d1.x + h1.y * d1.y + h1.z * d1.z + h1.w * d1.w;
    ps += __shfl_xor_sync(0xffffffffu, ps, 1); ps += __shfl_xor_sync(0xffffffffu, ps, 2);
    pd += __shfl_xor_sync(0xffffffffu, pd, 1); pd += __shfl_xor_sync(0xffffffffu, pd, 2);
    if ((lane & 3) == 0) {
        g_asrc[node * 8 + (lane >> 2)] = ps;
        g_adst[node * 8 + (lane >> 2)] = pd;
    }
}

// ---------------- K3: in-degree histogram (incl. self loops) ---------------
__global__ void k_hist(const int* __restrict__ ei) {
    int idx = blockIdx.x * blockDim.x + threadIdx.x;
    if (idx >= M_TOTAL) return;
    int d = (idx < N_EDGES) ? ei[N_EDGES + idx] : (idx - N_EDGES);
    atomicAdd(&g_deg[d], 1);
}

// ---------------- K4: exclusive scan of degrees (one block) ----------------
__global__ __launch_bounds__(1024)
void k_scan() {
    __shared__ int sums[1024];
    const int t = threadIdx.x;
    const int CH = (N_NODES + 1023) / 1024;         // 49
    int start = t * CH;
    int end   = start + CH; if (end > N_NODES) end = N_NODES;
    int s = 0;
    for (int i = start; i < end; i++) s += g_deg[i];
    sums[t] = s;
    __syncthreads();
    for (int off = 1; off < 1024; off <<= 1) {
        int add = (t >= off) ? sums[t - off] : 0;
        __syncthreads();
        sums[t] += add;
        __syncthreads();
    }
    int run = (t == 0) ? 0 : sums[t - 1];
    for (int i = start; i < end; i++) { g_off[i] = run; run += g_deg[i]; }
    if (t == 1023) g_off[N_NODES] = sums[1023];
}

// ---------------- K5: scatter edges into CSR (by dst) ----------------------
__global__ void k_scatter(const int* __restrict__ ei) {
    int idx = blockIdx.x * blockDim.x + threadIdx.x;
    if (idx >= M_TOTAL) return;
    int s, d;
    if (idx < N_EDGES) { s = ei[idx]; d = ei[N_EDGES + idx]; }
    else               { s = d = idx - N_EDGES; }
    int pos = g_off[d] + atomicAdd(&g_cursor[d], 1);
    g_csr_src[pos] = s;
}

// ---------------- K6: aggregation + ELU + mean-pool contribution -----------
// warp per node. grid = 6250 (exact). Normalization deferred: out = (Σ ex*h)/Σex
__global__ __launch_bounds__(256)
void k_aggr(const float* __restrict__ bias) {
    __shared__ float pool[8][256];
    const int warp = threadIdx.x >> 5, lane = threadIdx.x & 31;
    const int node = blockIdx.x * 8 + warp;
    const int head = lane >> 2;

    const int base = g_off[node];
    const int deg  = g_off[node + 1] - base;

    const float4* ad = (const float4*)(g_adst + node * 8);
    float4 A0 = ad[0], A1 = ad[1];
    float adv[8] = {A0.x, A0.y, A0.z, A0.w, A1.x, A1.y, A1.z, A1.w};

    // pass 1: segment max per head (lanes stride over edges)
    float mx[8];
    #pragma unroll
    for (int h = 0; h < 8; h++) mx[h] = -1e30f;
    for (int k = lane; k < deg; k += 32) {
        int s = g_csr_src[base + k];
        const float4* as = (const float4*)(g_asrc + s * 8);
        float4 S0 = as[0], S1 = as[1];
        float sv[8] = {S0.x, S0.y, S0.z, S0.w, S1.x, S1.y, S1.z, S1.w};
        #pragma unroll
        for (int h = 0; h < 8; h++) {
            float e = sv[h] + adv[h];
            e = (e > 0.f) ? e : NEG_SLOPE * e;
            mx[h] = fmaxf(mx[h], e);
        }
    }
    #pragma unroll
    for (int h = 0; h < 8; h++) {
        #pragma unroll
        for (int off = 16; off; off >>= 1)
            mx[h] = fmaxf(mx[h], __shfl_xor_sync(0xffffffffu, mx[h], off));
    }
    const float m_mine    = mx[head];
    const float adst_mine = adv[head];

    // pass 2: gather h[src], accumulate ex-weighted sum + denom
    float acc[8] = {0.f, 0.f, 0.f, 0.f, 0.f, 0.f, 0.f, 0.f};
    float denom = 0.f;
    for (int k = 0; k < deg; k++) {
        int s = g_csr_src[base + k];                // uniform across warp
        float asv = __ldg(&g_asrc[s * 8 + head]);
        float e = asv + adst_mine;
        e = (e > 0.f) ? e : NEG_SLOPE * e;
        float ex = __expf(e - m_mine);
        denom += ex;
        const float4* hp = (const float4*)(g_h + s * 256 + lane * 8);
        float4 h0 = hp[0], h1 = hp[1];
        acc[0] += ex * h0.x; acc[1] += ex * h0.y; acc[2] += ex * h0.z; acc[3] += ex * h0.w;
        acc[4] += ex * h1.x; acc[5] += ex * h1.y; acc[6] += ex * h1.z; acc[7] += ex * h1.w;
    }
    const float inv = 1.0f / (denom + 1e-16f);

    const float4* b4 = (const float4*)(bias + lane * 8);
    float4 B0 = b4[0], B1 = b4[1];
    float bv[8] = {B0.x, B0.y, B0.z, B0.w, B1.x, B1.y, B1.z, B1.w};
    float o[8];
    #pragma unroll
    for (int j = 0; j < 8; j++) {
        float v = acc[j] * inv + bv[j];
        o[j] = (v > 0.f) ? v : (__expf(v) - 1.0f);   // ELU(alpha=1)
    }
    *(float4*)&pool[warp][lane * 8]     = make_float4(o[0], o[1], o[2], o[3]);
    *(float4*)&pool[warp][lane * 8 + 4] = make_float4(o[4], o[5], o[6], o[7]);
    __syncthreads();

    const int t = threadIdx.x;  // 256 threads == 256 channels
    float sum = pool[0][t] + pool[1][t] + pool[2][t] + pool[3][t]
              + pool[4][t] + pool[5][t] + pool[6][t] + pool[7][t];
    atomicAdd(&g_pooled[t], sum);
}

// ---------------- K7: mean + MLP head --------------------------------------
__global__ __launch_bounds__(256)
void k_mlp(const float* __restrict__ W1, const float* __restrict__ b1,
           const float* __restrict__ W2, const float* __restrict__ b2,
           float* __restrict__ out) {
    __shared__ float p[256];
    __shared__ float z[128];
    const int t = threadIdx.x;
    p[t] = g_pooled[t] * (1.0f / (float)N_NODES);
    __syncthreads();
    if (t < 128) {
        float a = b1[t];
        #pragma unroll 8
        for (int k = 0; k < 256; k++) a += p[k] * W1[k * 128 + t];
        z[t] = fmaxf(a, 0.f);
    }
    __syncthreads();
    if (t < 6) {
        float a = b2[t];
        #pragma unroll 8
        for (int k = 0; k < 128; k++) a += z[k] * W2[k * 6 + t];
        out[t] = a;
    }
}

// ---------------- launch ----------------------------------------------------
extern "C" void kernel_launch(void* const* d_in, const int* in_sizes, int n_in,
                              void* d_out, int out_size) {
    const float* x        = (const float*)d_in[0];
    const int*   ei       = (const int*)  d_in[1];
    const float* W        = (const float*)d_in[2];
    const float* att_src  = (const float*)d_in[3];
    const float* att_dst  = (const float*)d_in[4];
    const float* bias     = (const float*)d_in[5];
    const float* W1       = (const float*)d_in[6];
    const float* b1       = (const float*)d_in[7];
    const float* W2       = (const float*)d_in[8];
    const float* b2       = (const float*)d_in[9];
    float* out = (float*)d_out;

    const int smem_gemm = (64 * 128 + 128 * 256) * sizeof(float);   // 163840
    cudaFuncSetAttribute(k_gemm, cudaFuncAttributeMaxDynamicSharedMemorySize, smem_gemm);

    k_init<<<(N_NODES + 255) / 256, 256>>>();
    k_gemm<<<(N_NODES + 63) / 64, 256, smem_gemm>>>(x, W);
    k_att<<<N_NODES / 8, 256>>>(att_src, att_dst);
    k_hist<<<(M_TOTAL + 255) / 256, 256>>>(ei);
    k_scan<<<1, 1024>>>();
    k_scatter<<<(M_TOTAL + 255) / 256, 256>>>(ei);
    k_aggr<<<N_NODES / 8, 256>>>(bias);
    k_mlp<<<1, 256>>>(W1, b1, W2, b2, out);
}

// round 8
// speedup vs baseline: 1.5678x; 1.5678x over previous
#include <cuda_runtime.h>
#include <cuda_bf16.h>
#include <math.h>
#include <stdint.h>

#define N_NODES 50000
#define N_EDGES 800000
#define M_TOTAL (N_EDGES + N_NODES)   // 850000 with self loops
#define HEADS   8
#define NEG_SLOPE 0.2f

// ---------------- scratch (static device globals) ---------------------------
__device__ uint32_t      g_hb[N_NODES * 128];     // h as packed bf16x2, 256 cols/row
__device__ __nv_bfloat16 g_Wt_hi[256 * 128];      // W^T hi  [N=256][K=128]
__device__ __nv_bfloat16 g_Wt_lo[256 * 128];      // W^T lo
__device__ float g_asrc[N_NODES * HEADS];
__device__ float g_adst[N_NODES * HEADS];
__device__ int   g_deg[N_NODES];
__device__ int   g_off[N_NODES + 1];
__device__ int   g_cursor[N_NODES];
__device__ int   g_csr_src[M_TOTAL];
__device__ float g_pooled[256];

// ---------------- K0: init ---------------------------------------------------
__global__ void k_init() {
    int i = blockIdx.x * blockDim.x + threadIdx.x;
    if (i < N_NODES) { g_deg[i] = 0; g_cursor[i] = 0; }
    if (i < 256)     g_pooled[i] = 0.0f;
}

// ---------------- K1: W -> W^T split hi/lo bf16 ------------------------------
__global__ void k_prep(const float* __restrict__ W) {   // W [128][256]
    int idx = blockIdx.x * blockDim.x + threadIdx.x;    // 32768
    int k = idx >> 8, n = idx & 255;                    // coalesced read
    float v = W[k * 256 + n];
    __nv_bfloat16 hi = __float2bfloat16(v);
    float lo = v - __bfloat162float(hi);
    g_Wt_hi[n * 128 + k] = hi;
    g_Wt_lo[n * 128 + k] = __float2bfloat16(lo);
}

// ---------------- K2: HMMA split-bf16 GEMM + attention epilogue --------------
// CTA tile: M=128 (blockIdx.x), N=128 (blockIdx.y), K=128 full.
// 8 warps as 4(m) x 2(n): warp tile 32x64. 3 passes: AhBh + AhBl + AlBh.
#define PITCHB 272                       // 136 bf16 per row (128 data + 8 pad)
#define OFF_ATTS  0                      // 128 f32
#define OFF_ATTD  512
#define OFF_A_HI  1024                   // 128 x 136 bf16 = 34816 B
#define OFF_A_LO  (OFF_A_HI + 34816)
#define OFF_B_HI  (OFF_A_LO + 34816)
#define OFF_B_LO  (OFF_B_HI + 34816)
#define SMEM_SZ   (OFF_B_LO + 34816)     // 140288 B

__device__ __forceinline__ void mma16816(float* c, uint32_t a0, uint32_t a1,
                                         uint32_t a2, uint32_t a3,
                                         uint32_t b0, uint32_t b1) {
    asm volatile(
        "mma.sync.aligned.m16n8k16.row.col.f32.bf16.bf16.f32 "
        "{%0,%1,%2,%3}, {%4,%5,%6,%7}, {%8,%9}, {%0,%1,%2,%3};"
        : "+f"(c[0]), "+f"(c[1]), "+f"(c[2]), "+f"(c[3])
        : "r"(a0), "r"(a1), "r"(a2), "r"(a3), "r"(b0), "r"(b1));
}

__global__ __launch_bounds__(256, 1)
void k_gemm_mma(const float* __restrict__ x,
                const float* __restrict__ att_src, const float* __restrict__ att_dst) {
    extern __shared__ char sm[];
    float* s_atts = (float*)(sm + OFF_ATTS);
    float* s_attd = (float*)(sm + OFF_ATTD);
    const int tid  = threadIdx.x;
    const int wid  = tid >> 5, lane = tid & 31;
    const int g    = lane >> 2, kq = lane & 3;
    const int wm   = wid & 3, wn = wid >> 2;       // warp grid 4x2
    const int row0 = blockIdx.x * 128;
    const int n0   = blockIdx.y * 128;

    if (tid < 128) { s_atts[tid] = att_src[n0 + tid]; s_attd[tid] = att_dst[n0 + tid]; }

    // ---- fill A (x rows, split hi/lo). warp => one row, 256B contiguous -> no conflicts
    const float4* X4 = (const float4*)x;
    #pragma unroll
    for (int it = 0; it < 16; it++) {
        int i   = tid + it * 256;                  // 4096 items
        int row = i >> 5, c4 = i & 31;
        int gr  = row0 + row;
        float4 v = (gr < N_NODES) ? X4[gr * 32 + c4] : make_float4(0.f, 0.f, 0.f, 0.f);
        __nv_bfloat16 bx = __float2bfloat16(v.x), by = __float2bfloat16(v.y);
        __nv_bfloat16 bz = __float2bfloat16(v.z), bw = __float2bfloat16(v.w);
        __nv_bfloat162 h0 = __halves2bfloat162(bx, by), h1 = __halves2bfloat162(bz, bw);
        __nv_bfloat162 l0 = __halves2bfloat162(__float2bfloat16(v.x - __bfloat162float(bx)),
                                               __float2bfloat16(v.y - __bfloat162float(by)));
        __nv_bfloat162 l1 = __halves2bfloat162(__float2bfloat16(v.z - __bfloat162float(bz)),
                                               __float2bfloat16(v.w - __bfloat162float(bw)));
        char* pa = sm + row * PITCHB + c4 * 8;
        *(uint2*)(pa + OFF_A_HI) = make_uint2(*(uint32_t*)&h0, *(uint32_t*)&h1);
        *(uint2*)(pa + OFF_A_LO) = make_uint2(*(uint32_t*)&l0, *(uint32_t*)&l1);
    }
    // ---- fill B slice [n0..n0+127][128]
    const int4* WH = (const int4*)g_Wt_hi;
    const int4* WL = (const int4*)g_Wt_lo;
    #pragma unroll
    for (int it = 0; it < 8; it++) {
        int i  = tid + it * 256;                   // 2048 items
        int n  = i >> 4, k8 = i & 15;
        int gi = (n0 + n) * 16 + k8;               // int4 index into [256][128] bf16
        char* pb = sm + n * PITCHB + k8 * 16;
        *(int4*)(pb + OFF_B_HI) = WH[gi];
        *(int4*)(pb + OFF_B_LO) = WL[gi];
    }
    __syncthreads();

    // ---- mainloop
    float acc[2][8][4];
    #pragma unroll
    for (int mi = 0; mi < 2; mi++)
        #pragma unroll
        for (int ni = 0; ni < 8; ni++)
            #pragma unroll
            for (int c = 0; c < 4; c++) acc[mi][ni][c] = 0.f;

    const int aoff = (wm * 32 + g) * PITCHB + kq * 4;
    const int boff = (wn * 64 + g) * PITCHB + kq * 4;

    #pragma unroll
    for (int pass = 0; pass < 3; pass++) {
        const char* As = sm + ((pass == 2) ? OFF_A_LO : OFF_A_HI);
        const char* Bs = sm + ((pass == 1) ? OFF_B_LO : OFF_B_HI);
        #pragma unroll 2
        for (int ks = 0; ks < 8; ks++) {
            uint32_t a[2][4];
            #pragma unroll
            for (int mi = 0; mi < 2; mi++) {
                const char* p = As + aoff + mi * (16 * PITCHB) + ks * 32;
                a[mi][0] = *(const uint32_t*)(p);
                a[mi][1] = *(const uint32_t*)(p + 8 * PITCHB);
                a[mi][2] = *(const uint32_t*)(p + 16);
                a[mi][3] = *(const uint32_t*)(p + 8 * PITCHB + 16);
            }
            uint32_t b[8][2];
            #pragma unroll
            for (int ni = 0; ni < 8; ni++) {
                const char* p = Bs + boff + ni * (8 * PITCHB) + ks * 32;
                b[ni][0] = *(const uint32_t*)(p);
                b[ni][1] = *(const uint32_t*)(p + 16);
            }
            #pragma unroll
            for (int mi = 0; mi < 2; mi++)
                #pragma unroll
                for (int ni = 0; ni < 8; ni++)
                    mma16816(acc[mi][ni], a[mi][0], a[mi][1], a[mi][2], a[mi][3],
                             b[ni][0], b[ni][1]);
        }
    }

    // ---- epilogue: pack bf16 h + attention logits
    #pragma unroll
    for (int mi = 0; mi < 2; mi++) {
        const int r_lo = row0 + wm * 32 + mi * 16 + g;
        const int r_hi = r_lo + 8;
        float sa[2][2] = {{0.f, 0.f}, {0.f, 0.f}};   // [rowgrp][head]
        float sd[2][2] = {{0.f, 0.f}, {0.f, 0.f}};
        #pragma unroll
        for (int ni = 0; ni < 8; ni++) {
            const int lh = ni >> 2;
            const int lc = wn * 64 + ni * 8 + kq * 2;
            const float as0 = s_atts[lc], as1 = s_atts[lc + 1];
            const float ad0 = s_attd[lc], ad1 = s_attd[lc + 1];
            const float c0 = acc[mi][ni][0], c1 = acc[mi][ni][1];
            const float c2 = acc[mi][ni][2], c3 = acc[mi][ni][3];
            sa[0][lh] += c0 * as0 + c1 * as1;
            sd[0][lh] += c0 * ad0 + c1 * ad1;
            sa[1][lh] += c2 * as0 + c3 * as1;
            sd[1][lh] += c2 * ad0 + c3 * ad1;
            // store packed bf16 pair
            __nv_bfloat162 p0 = __halves2bfloat162(__float2bfloat16(c0), __float2bfloat16(c1));
            __nv_bfloat162 p1 = __halves2bfloat162(__float2bfloat16(c2), __float2bfloat16(c3));
            const int cp = blockIdx.y * 64 + wn * 32 + ni * 4 + kq;  // colpair 0..127
            if (r_lo < N_NODES) g_hb[(size_t)r_lo * 128 + cp] = *(uint32_t*)&p0;
            if (r_hi < N_NODES) g_hb[(size_t)r_hi * 128 + cp] = *(uint32_t*)&p1;
        }
        // quad reduction (lanes kq 0..3 share the row)
        #pragma unroll
        for (int grp = 0; grp < 2; grp++)
            #pragma unroll
            for (int lh = 0; lh < 2; lh++) {
                sa[grp][lh] += __shfl_xor_sync(0xffffffffu, sa[grp][lh], 1);
                sa[grp][lh] += __shfl_xor_sync(0xffffffffu, sa[grp][lh], 2);
                sd[grp][lh] += __shfl_xor_sync(0xffffffffu, sd[grp][lh], 1);
                sd[grp][lh] += __shfl_xor_sync(0xffffffffu, sd[grp][lh], 2);
            }
        if (kq == 0) {
            const int gh0 = blockIdx.y * 4 + wn * 2;
            if (r_lo < N_NODES) {
                g_asrc[r_lo * 8 + gh0]     = sa[0][0];
                g_asrc[r_lo * 8 + gh0 + 1] = sa[0][1];
                g_adst[r_lo * 8 + gh0]     = sd[0][0];
                g_adst[r_lo * 8 + gh0 + 1] = sd[0][1];
            }
            if (r_hi < N_NODES) {
                g_asrc[r_hi * 8 + gh0]     = sa[1][0];
                g_asrc[r_hi * 8 + gh0 + 1] = sa[1][1];
                g_adst[r_hi * 8 + gh0]     = sd[1][0];
                g_adst[r_hi * 8 + gh0 + 1] = sd[1][1];
            }
        }
    }
}

// ---------------- K3: in-degree histogram ------------------------------------
__global__ void k_hist(const int* __restrict__ ei) {
    int idx = blockIdx.x * blockDim.x + threadIdx.x;
    if (idx >= M_TOTAL) return;
    int d = (idx < N_EDGES) ? ei[N_EDGES + idx] : (idx - N_EDGES);
    atomicAdd(&g_deg[d], 1);
}

// ---------------- K4: exclusive scan (one block) -----------------------------
__global__ __launch_bounds__(1024)
void k_scan() {
    __shared__ int sums[1024];
    const int t = threadIdx.x;
    const int CH = (N_NODES + 1023) / 1024;
    int start = t * CH;
    int end = start + CH; if (end > N_NODES) end = N_NODES;
    int s = 0;
    for (int i = start; i < end; i++) s += g_deg[i];
    sums[t] = s;
    __syncthreads();
    for (int off = 1; off < 1024; off <<= 1) {
        int add = (t >= off) ? sums[t - off] : 0;
        __syncthreads();
        sums[t] += add;
        __syncthreads();
    }
    int run = (t == 0) ? 0 : sums[t - 1];
    for (int i = start; i < end; i++) { g_off[i] = run; run += g_deg[i]; }
    if (t == 1023) g_off[N_NODES] = sums[1023];
}

// ---------------- K5: scatter into CSR (by dst) ------------------------------
__global__ void k_scatter(const int* __restrict__ ei) {
    int idx = blockIdx.x * blockDim.x + threadIdx.x;
    if (idx >= M_TOTAL) return;
    int s, d;
    if (idx < N_EDGES) { s = ei[idx]; d = ei[N_EDGES + idx]; }
    else               { s = d = idx - N_EDGES; }
    int pos = g_off[d] + atomicAdd(&g_cursor[d], 1);
    g_csr_src[pos] = s;
}

// ---------------- K6: single-pass softmax aggregation + ELU + pool -----------
// warp per node; no segment-max (shift-invariant softmax, small logits)
__global__ __launch_bounds__(256)
void k_aggr(const float* __restrict__ bias) {
    __shared__ float pool[8][256];
    const int warp = threadIdx.x >> 5, lane = threadIdx.x & 31;
    const int node = blockIdx.x * 8 + warp;
    const int head = lane >> 2;

    const int base = g_off[node];
    const int deg  = g_off[node + 1] - base;
    const float adst_mine = g_adst[node * 8 + head];

    float acc[8] = {0.f, 0.f, 0.f, 0.f, 0.f, 0.f, 0.f, 0.f};
    float denom = 0.f;
    for (int k = 0; k < deg; k++) {
        int s = g_csr_src[base + k];
        float asv = __ldg(&g_asrc[s * 8 + head]);
        float e = asv + adst_mine;
        e = (e > 0.f) ? e : NEG_SLOPE * e;
        float ex = __expf(e);
        denom += ex;
        uint4 p = *(const uint4*)(g_hb + (size_t)s * 128 + lane * 4);
        float2 f0 = __bfloat1622float2(*(__nv_bfloat162*)&p.x);
        float2 f1 = __bfloat1622float2(*(__nv_bfloat162*)&p.y);
        float2 f2 = __bfloat1622float2(*(__nv_bfloat162*)&p.z);
        float2 f3 = __bfloat1622float2(*(__nv_bfloat162*)&p.w);
        acc[0] += ex * f0.x; acc[1] += ex * f0.y;
        acc[2] += ex * f1.x; acc[3] += ex * f1.y;
        acc[4] += ex * f2.x; acc[5] += ex * f2.y;
        acc[6] += ex * f3.x; acc[7] += ex * f3.y;
    }
    const float inv = 1.0f / (denom + 1e-16f);

    const float4* b4 = (const float4*)(bias + lane * 8);
    float4 B0 = b4[0], B1 = b4[1];
    float bv[8] = {B0.x, B0.y, B0.z, B0.w, B1.x, B1.y, B1.z, B1.w};
    float o[8];
    #pragma unroll
    for (int j = 0; j < 8; j++) {
        float v = acc[j] * inv + bv[j];
        o[j] = (v > 0.f) ? v : (__expf(v) - 1.0f);
    }
    *(float4*)&pool[warp][lane * 8]     = make_float4(o[0], o[1], o[2], o[3]);
    *(float4*)&pool[warp][lane * 8 + 4] = make_float4(o[4], o[5], o[6], o[7]);
    __syncthreads();

    const int t = threadIdx.x;
    float sum = pool[0][t] + pool[1][t] + pool[2][t] + pool[3][t]
              + pool[4][t] + pool[5][t] + pool[6][t] + pool[7][t];
    atomicAdd(&g_pooled[t], sum);
}

// ---------------- K7: mean + MLP head ----------------------------------------
__global__ __launch_bounds__(256)
void k_mlp(const float* __restrict__ W1, const float* __restrict__ b1,
           const float* __restrict__ W2, const float* __restrict__ b2,
           float* __restrict__ out) {
    __shared__ float p[256];
    __shared__ float z[128];
    const int t = threadIdx.x;
    p[t] = g_pooled[t] * (1.0f / (float)N_NODES);
    __syncthreads();
    if (t < 128) {
        float a = b1[t];
        #pragma unroll 8
        for (int k = 0; k < 256; k++) a += p[k] * W1[k * 128 + t];
        z[t] = fmaxf(a, 0.f);
    }
    __syncthreads();
    if (t < 6) {
        float a = b2[t];
        #pragma unroll 8
        for (int k = 0; k < 128; k++) a += z[k] * W2[k * 6 + t];
        out[t] = a;
    }
}

// ---------------- launch ------------------------------------------------------
extern "C" void kernel_launch(void* const* d_in, const int* in_sizes, int n_in,
                              void* d_out, int out_size) {
    const float* x       = (const float*)d_in[0];
    const int*   ei      = (const int*)  d_in[1];
    const float* W       = (const float*)d_in[2];
    const float* att_src = (const float*)d_in[3];
    const float* att_dst = (const float*)d_in[4];
    const float* bias    = (const float*)d_in[5];
    const float* W1      = (const float*)d_in[6];
    const float* b1      = (const float*)d_in[7];
    const float* W2      = (const float*)d_in[8];
    const float* b2      = (const float*)d_in[9];
    float* out = (float*)d_out;

    cudaFuncSetAttribute(k_gemm_mma, cudaFuncAttributeMaxDynamicSharedMemorySize, SMEM_SZ);

    k_init<<<(N_NODES + 255) / 256, 256>>>();
    k_prep<<<128, 256>>>(W);
    dim3 ggrid((N_NODES + 127) / 128, 2);
    k_gemm_mma<<<ggrid, 256, SMEM_SZ>>>(x, att_src, att_dst);
    k_hist<<<(M_TOTAL + 255) / 256, 256>>>(ei);
    k_scan<<<1, 1024>>>();
    k_scatter<<<(M_TOTAL + 255) / 256, 256>>>(ei);
    k_aggr<<<N_NODES / 8, 256>>>(bias);
    k_mlp<<<1, 256>>>(W1, b1, W2, b2, out);
}

// round 9
// speedup vs baseline: 1.6080x; 1.0256x over previous
#include <cuda_runtime.h>
#include <cuda_bf16.h>
#include <math.h>
#include <stdint.h>

#define N_NODES 50000
#define N_EDGES 800000
#define M_TOTAL (N_EDGES + N_NODES)   // 850000 with self loops
#define HEADS   8
#define NEG_SLOPE 0.2f

// ---------------- scratch (static device globals) ---------------------------
__device__ uint32_t      g_hb[N_NODES * 128];     // h as packed bf16x2, 256 cols/row
__device__ __nv_bfloat16 g_Wt_hi[256 * 128];      // W^T hi  [N=256][K=128]
__device__ __nv_bfloat16 g_Wt_lo[256 * 128];      // W^T lo
__device__ float g_asrc[N_NODES * HEADS];
__device__ float g_adst[N_NODES * HEADS];
__device__ int   g_deg[N_NODES];
__device__ int   g_off[N_NODES + 1];
__device__ int   g_cursor[N_NODES];
__device__ int   g_csr_src[M_TOTAL];
__device__ float g_pooled[256];

// ---------------- K0: init (deg=1 accounts for the self loop) ----------------
__global__ void k_init() {
    int i = blockIdx.x * blockDim.x + threadIdx.x;
    if (i < N_NODES) g_deg[i] = 1;
    if (i < 256)     g_pooled[i] = 0.0f;
}

// ---------------- K1: W -> W^T split hi/lo bf16 ------------------------------
__global__ void k_prep(const float* __restrict__ W) {   // W [128][256]
    int idx = blockIdx.x * blockDim.x + threadIdx.x;    // 32768
    int k = idx >> 8, n = idx & 255;                    // coalesced read
    float v = W[k * 256 + n];
    __nv_bfloat16 hi = __float2bfloat16(v);
    float lo = v - __bfloat162float(hi);
    g_Wt_hi[n * 128 + k] = hi;
    g_Wt_lo[n * 128 + k] = __float2bfloat16(lo);
}

// ---------------- K2: HMMA split-bf16 GEMM + attention epilogue --------------
// CTA tile: M=128 (blockIdx.x), N=128 (blockIdx.y), K=128 full.
// 8 warps as 4(m) x 2(n): warp tile 32x64. 3 passes: AhBh + AhBl + AlBh.
#define PITCHB 272                       // 136 bf16 per row (128 data + 8 pad)
#define OFF_ATTS  0                      // 128 f32
#define OFF_ATTD  512
#define OFF_A_HI  1024                   // 128 x 136 bf16 = 34816 B
#define OFF_A_LO  (OFF_A_HI + 34816)
#define OFF_B_HI  (OFF_A_LO + 34816)
#define OFF_B_LO  (OFF_B_HI + 34816)
#define SMEM_SZ   (OFF_B_LO + 34816)     // 140288 B

__device__ __forceinline__ void mma16816(float* c, uint32_t a0, uint32_t a1,
                                         uint32_t a2, uint32_t a3,
                                         uint32_t b0, uint32_t b1) {
    asm volatile(
        "mma.sync.aligned.m16n8k16.row.col.f32.bf16.bf16.f32 "
        "{%0,%1,%2,%3}, {%4,%5,%6,%7}, {%8,%9}, {%0,%1,%2,%3};"
        : "+f"(c[0]), "+f"(c[1]), "+f"(c[2]), "+f"(c[3])
        : "r"(a0), "r"(a1), "r"(a2), "r"(a3), "r"(b0), "r"(b1));
}

__global__ __launch_bounds__(256, 1)
void k_gemm_mma(const float* __restrict__ x,
                const float* __restrict__ att_src, const float* __restrict__ att_dst) {
    extern __shared__ char sm[];
    float* s_atts = (float*)(sm + OFF_ATTS);
    float* s_attd = (float*)(sm + OFF_ATTD);
    const int tid  = threadIdx.x;
    const int wid  = tid >> 5, lane = tid & 31;
    const int g    = lane >> 2, kq = lane & 3;
    const int wm   = wid & 3, wn = wid >> 2;       // warp grid 4x2
    const int row0 = blockIdx.x * 128;
    const int n0   = blockIdx.y * 128;

    if (tid < 128) { s_atts[tid] = att_src[n0 + tid]; s_attd[tid] = att_dst[n0 + tid]; }

    // ---- fill A (x rows, split hi/lo)
    const float4* X4 = (const float4*)x;
    #pragma unroll
    for (int it = 0; it < 16; it++) {
        int i   = tid + it * 256;                  // 4096 items
        int row = i >> 5, c4 = i & 31;
        int gr  = row0 + row;
        float4 v = (gr < N_NODES) ? X4[gr * 32 + c4] : make_float4(0.f, 0.f, 0.f, 0.f);
        __nv_bfloat16 bx = __float2bfloat16(v.x), by = __float2bfloat16(v.y);
        __nv_bfloat16 bz = __float2bfloat16(v.z), bw = __float2bfloat16(v.w);
        __nv_bfloat162 h0 = __halves2bfloat162(bx, by), h1 = __halves2bfloat162(bz, bw);
        __nv_bfloat162 l0 = __halves2bfloat162(__float2bfloat16(v.x - __bfloat162float(bx)),
                                               __float2bfloat16(v.y - __bfloat162float(by)));
        __nv_bfloat162 l1 = __halves2bfloat162(__float2bfloat16(v.z - __bfloat162float(bz)),
                                               __float2bfloat16(v.w - __bfloat162float(bw)));
        char* pa = sm + row * PITCHB + c4 * 8;
        *(uint2*)(pa + OFF_A_HI) = make_uint2(*(uint32_t*)&h0, *(uint32_t*)&h1);
        *(uint2*)(pa + OFF_A_LO) = make_uint2(*(uint32_t*)&l0, *(uint32_t*)&l1);
    }
    // ---- fill B slice [n0..n0+127][128]
    const int4* WH = (const int4*)g_Wt_hi;
    const int4* WL = (const int4*)g_Wt_lo;
    #pragma unroll
    for (int it = 0; it < 8; it++) {
        int i  = tid + it * 256;                   // 2048 items
        int n  = i >> 4, k8 = i & 15;
        int gi = (n0 + n) * 16 + k8;               // int4 index into [256][128] bf16
        char* pb = sm + n * PITCHB + k8 * 16;
        *(int4*)(pb + OFF_B_HI) = WH[gi];
        *(int4*)(pb + OFF_B_LO) = WL[gi];
    }
    __syncthreads();

    // ---- mainloop
    float acc[2][8][4];
    #pragma unroll
    for (int mi = 0; mi < 2; mi++)
        #pragma unroll
        for (int ni = 0; ni < 8; ni++)
            #pragma unroll
            for (int c = 0; c < 4; c++) acc[mi][ni][c] = 0.f;

    const int aoff = (wm * 32 + g) * PITCHB + kq * 4;
    const int boff = (wn * 64 + g) * PITCHB + kq * 4;

    #pragma unroll
    for (int pass = 0; pass < 3; pass++) {
        const char* As = sm + ((pass == 2) ? OFF_A_LO : OFF_A_HI);
        const char* Bs = sm + ((pass == 1) ? OFF_B_LO : OFF_B_HI);
        #pragma unroll 2
        for (int ks = 0; ks < 8; ks++) {
            uint32_t a[2][4];
            #pragma unroll
            for (int mi = 0; mi < 2; mi++) {
                const char* p = As + aoff + mi * (16 * PITCHB) + ks * 32;
                a[mi][0] = *(const uint32_t*)(p);
                a[mi][1] = *(const uint32_t*)(p + 8 * PITCHB);
                a[mi][2] = *(const uint32_t*)(p + 16);
                a[mi][3] = *(const uint32_t*)(p + 8 * PITCHB + 16);
            }
            uint32_t b[8][2];
            #pragma unroll
            for (int ni = 0; ni < 8; ni++) {
                const char* p = Bs + boff + ni * (8 * PITCHB) + ks * 32;
                b[ni][0] = *(const uint32_t*)(p);
                b[ni][1] = *(const uint32_t*)(p + 16);
            }
            #pragma unroll
            for (int mi = 0; mi < 2; mi++)
                #pragma unroll
                for (int ni = 0; ni < 8; ni++)
                    mma16816(acc[mi][ni], a[mi][0], a[mi][1], a[mi][2], a[mi][3],
                             b[ni][0], b[ni][1]);
        }
    }

    // ---- epilogue: pack bf16 h + attention logits
    #pragma unroll
    for (int mi = 0; mi < 2; mi++) {
        const int r_lo = row0 + wm * 32 + mi * 16 + g;
        const int r_hi = r_lo + 8;
        float sa[2][2] = {{0.f, 0.f}, {0.f, 0.f}};   // [rowgrp][head]
        float sd[2][2] = {{0.f, 0.f}, {0.f, 0.f}};
        #pragma unroll
        for (int ni = 0; ni < 8; ni++) {
            const int lh = ni >> 2;
            const int lc = wn * 64 + ni * 8 + kq * 2;
            const float as0 = s_atts[lc], as1 = s_atts[lc + 1];
            const float ad0 = s_attd[lc], ad1 = s_attd[lc + 1];
            const float c0 = acc[mi][ni][0], c1 = acc[mi][ni][1];
            const float c2 = acc[mi][ni][2], c3 = acc[mi][ni][3];
            sa[0][lh] += c0 * as0 + c1 * as1;
            sd[0][lh] += c0 * ad0 + c1 * ad1;
            sa[1][lh] += c2 * as0 + c3 * as1;
            sd[1][lh] += c2 * ad0 + c3 * ad1;
            __nv_bfloat162 p0 = __halves2bfloat162(__float2bfloat16(c0), __float2bfloat16(c1));
            __nv_bfloat162 p1 = __halves2bfloat162(__float2bfloat16(c2), __float2bfloat16(c3));
            const int cp = blockIdx.y * 64 + wn * 32 + ni * 4 + kq;  // colpair 0..127
            if (r_lo < N_NODES) g_hb[(size_t)r_lo * 128 + cp] = *(uint32_t*)&p0;
            if (r_hi < N_NODES) g_hb[(size_t)r_hi * 128 + cp] = *(uint32_t*)&p1;
        }
        #pragma unroll
        for (int grp = 0; grp < 2; grp++)
            #pragma unroll
            for (int lh = 0; lh < 2; lh++) {
                sa[grp][lh] += __shfl_xor_sync(0xffffffffu, sa[grp][lh], 1);
                sa[grp][lh] += __shfl_xor_sync(0xffffffffu, sa[grp][lh], 2);
                sd[grp][lh] += __shfl_xor_sync(0xffffffffu, sd[grp][lh], 1);
                sd[grp][lh] += __shfl_xor_sync(0xffffffffu, sd[grp][lh], 2);
            }
        if (kq == 0) {
            const int gh0 = blockIdx.y * 4 + wn * 2;
            if (r_lo < N_NODES) {
                g_asrc[r_lo * 8 + gh0]     = sa[0][0];
                g_asrc[r_lo * 8 + gh0 + 1] = sa[0][1];
                g_adst[r_lo * 8 + gh0]     = sd[0][0];
                g_adst[r_lo * 8 + gh0 + 1] = sd[0][1];
            }
            if (r_hi < N_NODES) {
                g_asrc[r_hi * 8 + gh0]     = sa[1][0];
                g_asrc[r_hi * 8 + gh0 + 1] = sa[1][1];
                g_adst[r_hi * 8 + gh0]     = sd[1][0];
                g_adst[r_hi * 8 + gh0 + 1] = sd[1][1];
            }
        }
    }
}

// ---------------- K3: in-degree histogram (real edges only; grid-stride) -----
__global__ void k_hist(const int* __restrict__ ei) {
    const int t  = blockIdx.x * blockDim.x + threadIdx.x;
    const int NT = gridDim.x * blockDim.x;
    #pragma unroll 4
    for (int e = t; e < N_EDGES; e += NT)
        atomicAdd(&g_deg[ei[N_EDGES + e]], 1);
}

// ---------------- K4: coalesced tiled scan; seeds cursor + self-loop slot ----
__global__ __launch_bounds__(1024)
void k_scan() {
    __shared__ int ws[32];
    __shared__ int carry_s;
    const int t = threadIdx.x, lane = t & 31, w = t >> 5;
    if (t == 0) carry_s = 0;
    __syncthreads();
    for (int base = 0; base < N_NODES; base += 1024) {
        const int i = base + t;
        const int v = (i < N_NODES) ? g_deg[i] : 0;
        int x = v;
        #pragma unroll
        for (int o = 1; o < 32; o <<= 1) {
            int y = __shfl_up_sync(0xffffffffu, x, o);
            if (lane >= o) x += y;
        }
        if (lane == 31) ws[w] = x;
        __syncthreads();
        if (w == 0) {
            int s = ws[lane];
            #pragma unroll
            for (int o = 1; o < 32; o <<= 1) {
                int y = __shfl_up_sync(0xffffffffu, s, o);
                if (lane >= o) s += y;
            }
            ws[lane] = s;
        }
        __syncthreads();
        const int pre = carry_s + (w ? ws[w - 1] : 0) + x - v;   // exclusive
        if (i < N_NODES) {
            g_off[i]     = pre;
            g_csr_src[pre] = i;       // self loop occupies the first slot
            g_cursor[i]  = pre + 1;
        }
        __syncthreads();
        if (t == 1023) carry_s = pre + v;
        __syncthreads();
    }
    if (t == 1023) g_off[N_NODES] = carry_s;
}

// ---------------- K5: scatter real edges into CSR (by dst; grid-stride) ------
__global__ void k_scatter(const int* __restrict__ ei) {
    const int t  = blockIdx.x * blockDim.x + threadIdx.x;
    const int NT = gridDim.x * blockDim.x;
    #pragma unroll 4
    for (int e = t; e < N_EDGES; e += NT) {
        int s = ei[e], d = ei[N_EDGES + e];
        int pos = atomicAdd(&g_cursor[d], 1);
        g_csr_src[pos] = s;
    }
}

// ---------------- K6: single-pass softmax aggregation + ELU + pool -----------
__global__ __launch_bounds__(256)
void k_aggr(const float* __restrict__ bias) {
    __shared__ float pool[8][256];
    const int warp = threadIdx.x >> 5, lane = threadIdx.x & 31;
    const int node = blockIdx.x * 8 + warp;
    const int head = lane >> 2;

    const int base = g_off[node];
    const int deg  = g_off[node + 1] - base;
    const float adst_mine = g_adst[node * 8 + head];

    float acc[8] = {0.f, 0.f, 0.f, 0.f, 0.f, 0.f, 0.f, 0.f};
    float denom = 0.f;
    #pragma unroll 2
    for (int k = 0; k < deg; k++) {
        int s = g_csr_src[base + k];
        float asv = __ldg(&g_asrc[s * 8 + head]);
        float e = asv + adst_mine;
        e = (e > 0.f) ? e : NEG_SLOPE * e;
        float ex = __expf(e);
        denom += ex;
        uint4 p = *(const uint4*)(g_hb + (size_t)s * 128 + lane * 4);
        float2 f0 = __bfloat1622float2(*(__nv_bfloat162*)&p.x);
        float2 f1 = __bfloat1622float2(*(__nv_bfloat162*)&p.y);
        float2 f2 = __bfloat1622float2(*(__nv_bfloat162*)&p.z);
        float2 f3 = __bfloat1622float2(*(__nv_bfloat162*)&p.w);
        acc[0] += ex * f0.x; acc[1] += ex * f0.y;
        acc[2] += ex * f1.x; acc[3] += ex * f1.y;
        acc[4] += ex * f2.x; acc[5] += ex * f2.y;
        acc[6] += ex * f3.x; acc[7] += ex * f3.y;
    }
    const float inv = 1.0f / (denom + 1e-16f);

    const float4* b4 = (const float4*)(bias + lane * 8);
    float4 B0 = b4[0], B1 = b4[1];
    float bv[8] = {B0.x, B0.y, B0.z, B0.w, B1.x, B1.y, B1.z, B1.w};
    float o[8];
    #pragma unroll
    for (int j = 0; j < 8; j++) {
        float v = acc[j] * inv + bv[j];
        o[j] = (v > 0.f) ? v : (__expf(v) - 1.0f);
    }
    *(float4*)&pool[warp][lane * 8]     = make_float4(o[0], o[1], o[2], o[3]);
    *(float4*)&pool[warp][lane * 8 + 4] = make_float4(o[4], o[5], o[6], o[7]);
    __syncthreads();

    const int t = threadIdx.x;
    float sum = pool[0][t] + pool[1][t] + pool[2][t] + pool[3][t]
              + pool[4][t] + pool[5][t] + pool[6][t] + pool[7][t];
    atomicAdd(&g_pooled[t], sum);
}

// ---------------- K7: mean + MLP head ----------------------------------------
__global__ __launch_bounds__(256)
void k_mlp(const float* __restrict__ W1, const float* __restrict__ b1,
           const float* __restrict__ W2, const float* __restrict__ b2,
           float* __restrict__ out) {
    __shared__ float p[256];
    __shared__ float z[128];
    const int t = threadIdx.x;
    p[t] = g_pooled[t] * (1.0f / (float)N_NODES);
    __syncthreads();
    if (t < 128) {
        float a = b1[t];
        #pragma unroll 8
        for (int k = 0; k < 256; k++) a += p[k] * W1[k * 128 + t];
        z[t] = fmaxf(a, 0.f);
    }
    __syncthreads();
    if (t < 6) {
        float a = b2[t];
        #pragma unroll 8
        for (int k = 0; k < 128; k++) a += z[k] * W2[k * 6 + t];
        out[t] = a;
    }
}

// ---------------- side stream + events (created at static-init, pre-harness) -
struct HxStreams {
    cudaStream_t s2;
    cudaEvent_t  evFork, evJoin;
    HxStreams() {
        cudaStreamCreateWithFlags(&s2, cudaStreamNonBlocking);
        cudaEventCreateWithFlags(&evFork, cudaEventDisableTiming);
        cudaEventCreateWithFlags(&evJoin, cudaEventDisableTiming);
    }
};
static HxStreams g_hx;

// ---------------- launch ------------------------------------------------------
extern "C" void kernel_launch(void* const* d_in, const int* in_sizes, int n_in,
                              void* d_out, int out_size) {
    const float* x       = (const float*)d_in[0];
    const int*   ei      = (const int*)  d_in[1];
    const float* W       = (const float*)d_in[2];
    const float* att_src = (const float*)d_in[3];
    const float* att_dst = (const float*)d_in[4];
    const float* bias    = (const float*)d_in[5];
    const float* W1      = (const float*)d_in[6];
    const float* b1      = (const float*)d_in[7];
    const float* W2      = (const float*)d_in[8];
    const float* b2      = (const float*)d_in[9];
    float* out = (float*)d_out;

    cudaFuncSetAttribute(k_gemm_mma, cudaFuncAttributeMaxDynamicSharedMemorySize, SMEM_SZ);

    // fork: CSR-build chain on side stream, independent of GEMM chain
    cudaEventRecord(g_hx.evFork, 0);
    cudaStreamWaitEvent(g_hx.s2, g_hx.evFork, 0);

    k_init   <<<(N_NODES + 255) / 256, 256, 0, g_hx.s2>>>();
    k_hist   <<<800, 256, 0, g_hx.s2>>>(ei);
    k_scan   <<<1, 1024, 0, g_hx.s2>>>();
    k_scatter<<<800, 256, 0, g_hx.s2>>>(ei);
    cudaEventRecord(g_hx.evJoin, g_hx.s2);

    // main (capture) stream: GEMM chain
    k_prep<<<128, 256>>>(W);
    dim3 ggrid((N_NODES + 127) / 128, 2);
    k_gemm_mma<<<ggrid, 256, SMEM_SZ>>>(x, att_src, att_dst);

    // join, then aggregation + head
    cudaStreamWaitEvent(0, g_hx.evJoin, 0);
    k_aggr<<<N_NODES / 8, 256>>>(bias);
    k_mlp<<<1, 256>>>(W1, b1, W2, b2, out);
}